// round 1
// baseline (speedup 1.0000x reference)
#include <cuda_runtime.h>

#define BB 2
#define DD 160
#define HH 192
#define WW 160
#define HW (HH*WW)               // 30720
#define DHW (DD*HH*WW)           // 4,915,200
#define NVOX (BB*DD*HH*WW)       // 9,830,400
#define WIN3F 729.0f
#define INV_WIN3 (1.0f/729.0f)

#define SEG_H 4
#define SEGLEN_H (HH/SEG_H)      // 48
#define SEG_D 4
#define SEGLEN_D (DD/SEG_D)      // 40

#define ROWS_PER_BLK 4
#define NROWS (BB*DD*HH)         // 61440
#define NBLK_W (NROWS/ROWS_PER_BLK)  // 15360

// Scratch: 5 channels x NVOX, double-buffered between passes (~393 MB bss).
__device__ float g_buf1[5ULL * NVOX];
__device__ float g_buf2[5ULL * NVOX];
__device__ double g_partials[NBLK_W];

// ---------------------------------------------------------------------------
// Pass 1: compute 5 stats (I, J, I^2, J^2, I*J) and box-sum along H (rolling).
// One thread per (seg, b, d, w) column. Coalesced over w.
// ---------------------------------------------------------------------------
__global__ void pass_h_kernel(const float* __restrict__ I,
                              const float* __restrict__ J) {
    const int cols = BB * DD * WW;  // 51200
    int tid = blockIdx.x * blockDim.x + threadIdx.x;
    if (tid >= cols * SEG_H) return;
    int col = tid % cols;
    int seg = tid / cols;
    int b  = col / (DD * WW);
    int dw = col % (DD * WW);
    int d  = dw / WW;
    int w  = dw % WW;
    int base = ((b * DD + d) * HH) * WW + w;  // (b,d,0,w)
    int h0 = seg * SEGLEN_H;
    int h1 = h0 + SEGLEN_H;

    float s0 = 0.f, s1 = 0.f, s2 = 0.f, s3 = 0.f, s4 = 0.f;

    // Prime: window for h_out=h0 covers [h0-4, h0+4]; pre-add [h0-4, h0+3].
    for (int h = (h0 - 4 > 0 ? h0 - 4 : 0); h < h0 + 4; ++h) {
        float i = I[base + h * WW];
        float j = J[base + h * WW];
        s0 += i; s1 += j; s2 += i * i; s3 += j * j; s4 += i * j;
    }

    for (int ho = h0; ho < h1; ++ho) {
        int ha = ho + 4;
        if (ha < HH) {
            float i = I[base + ha * WW];
            float j = J[base + ha * WW];
            s0 += i; s1 += j; s2 += i * i; s3 += j * j; s4 += i * j;
        }
        int o = base + ho * WW;
        g_buf1[0 * NVOX + o] = s0;
        g_buf1[1 * NVOX + o] = s1;
        g_buf1[2 * NVOX + o] = s2;
        g_buf1[3 * NVOX + o] = s3;
        g_buf1[4 * NVOX + o] = s4;
        int hs = ho - 4;
        if (hs >= 0) {
            float i = I[base + hs * WW];   // L1/L2 hit: read 8 iters ago
            float j = J[base + hs * WW];
            s0 -= i; s1 -= j; s2 -= i * i; s3 -= j * j; s4 -= i * j;
        }
    }
}

// ---------------------------------------------------------------------------
// Pass 2: box-sum along D (rolling), one thread per (channel, seg, b, h, w).
// ---------------------------------------------------------------------------
__global__ void pass_d_kernel() {
    const int cols = BB * HW;  // 61440
    int tid = blockIdx.x * blockDim.x + threadIdx.x;
    if (tid >= cols * SEG_D * 5) return;
    int col  = tid % cols;
    int rest = tid / cols;
    int seg  = rest % SEG_D;
    int c    = rest / SEG_D;
    int b  = col / HW;
    int hw = col % HW;
    int base = c * NVOX + b * DHW + hw;  // (c,b,0,h,w)
    int d0 = seg * SEGLEN_D;
    int d1 = d0 + SEGLEN_D;

    float s = 0.f;
    for (int d = (d0 - 4 > 0 ? d0 - 4 : 0); d < d0 + 4; ++d)
        s += g_buf1[base + d * HW];

    for (int dd = d0; dd < d1; ++dd) {
        int da = dd + 4;
        if (da < DD) s += g_buf1[base + da * HW];
        g_buf2[base + dd * HW] = s;
        int ds = dd - 4;
        if (ds >= 0) s -= g_buf1[base + ds * HW];
    }
}

// ---------------------------------------------------------------------------
// Pass 3: box-sum along W (from shared), fused cc math + block reduction.
// Block = ROWS_PER_BLK rows of W=160 threads each (640 threads = 20 warps).
// ---------------------------------------------------------------------------
__global__ void pass_w_cc_kernel() {
    __shared__ float sm[ROWS_PER_BLK][5][WW];
    __shared__ float warpsum[ROWS_PER_BLK * (WW / 32)];  // 20 warps

    int ty = threadIdx.y;
    int w  = threadIdx.x;
    int row = blockIdx.x * ROWS_PER_BLK + ty;   // over (b,d,h)
    int base = row * WW;

    #pragma unroll
    for (int c = 0; c < 5; ++c)
        sm[ty][c][w] = g_buf2[c * NVOX + base + w];
    __syncthreads();

    float s0 = 0.f, s1 = 0.f, s2 = 0.f, s3 = 0.f, s4 = 0.f;
    #pragma unroll
    for (int k = -4; k <= 4; ++k) {
        int ww = w + k;
        if (ww >= 0 && ww < WW) {
            s0 += sm[ty][0][ww];
            s1 += sm[ty][1][ww];
            s2 += sm[ty][2][ww];
            s3 += sm[ty][3][ww];
            s4 += sm[ty][4][ww];
        }
    }

    float u_I = s0 * INV_WIN3;
    float u_J = s1 * INV_WIN3;
    float cross = s4 - u_J * s0 - u_I * s1 + u_I * u_J * WIN3F;
    float I_var = s2 - 2.0f * u_I * s0 + u_I * u_I * WIN3F;
    float J_var = s3 - 2.0f * u_J * s1 + u_J * u_J * WIN3F;
    float cc = cross * cross / (I_var * J_var + 1e-5f);

    // Reduce 640 threads -> 1 double partial per block. 160 = 5 full warps/row.
    float f = cc;
    #pragma unroll
    for (int off = 16; off; off >>= 1)
        f += __shfl_down_sync(0xffffffffu, f, off);
    int lin  = ty * WW + w;
    int lane = lin & 31;
    int wid  = lin >> 5;   // 0..19
    if (lane == 0) warpsum[wid] = f;
    __syncthreads();
    if (lin == 0) {
        double t = 0.0;
        #pragma unroll
        for (int i = 0; i < ROWS_PER_BLK * (WW / 32); ++i)
            t += (double)warpsum[i];
        g_partials[blockIdx.x] = t;
    }
}

// ---------------------------------------------------------------------------
// Final: sum partials, divide by N, write scalar.
// ---------------------------------------------------------------------------
__global__ void finalize_kernel(float* __restrict__ out) {
    __shared__ double sm[32];
    double t = 0.0;
    for (int i = threadIdx.x; i < NBLK_W; i += blockDim.x)
        t += g_partials[i];
    #pragma unroll
    for (int off = 16; off; off >>= 1)
        t += __shfl_down_sync(0xffffffffu, t, off);
    if ((threadIdx.x & 31) == 0) sm[threadIdx.x >> 5] = t;
    __syncthreads();
    if (threadIdx.x < 32) {
        double v = (threadIdx.x < (blockDim.x >> 5)) ? sm[threadIdx.x] : 0.0;
        #pragma unroll
        for (int off = 16; off; off >>= 1)
            v += __shfl_down_sync(0xffffffffu, v, off);
        if (threadIdx.x == 0) out[0] = (float)(v / (double)NVOX);
    }
}

extern "C" void kernel_launch(void* const* d_in, const int* in_sizes, int n_in,
                              void* d_out, int out_size) {
    const float* I = (const float*)d_in[0];  // predicted
    const float* J = (const float*)d_in[1];  // target

    {
        int threads = BB * DD * WW * SEG_H;          // 204,800
        pass_h_kernel<<<(threads + 255) / 256, 256>>>(I, J);
    }
    {
        int threads = BB * HW * SEG_D * 5;           // 1,228,800
        pass_d_kernel<<<(threads + 255) / 256, 256>>>();
    }
    {
        dim3 blk(WW, ROWS_PER_BLK);                  // 160 x 4 = 640
        pass_w_cc_kernel<<<NBLK_W, blk>>>();
    }
    finalize_kernel<<<1, 1024>>>((float*)d_out);
}

// round 2
// speedup vs baseline: 1.4736x; 1.4736x over previous
#include <cuda_runtime.h>

#define BB 2
#define DD 160
#define HH 192
#define WW 160
#define HW (HH*WW)               // 30720
#define DHW (DD*HH*WW)           // 4,915,200
#define NVOX (BB*DD*HH*WW)       // 9,830,400
#define INV_WIN3 (1.0f/729.0f)

// ---------------- Kernel A tiling ----------------
#define TH 16
#define HALO_R (TH+8)            // 24 halo rows
#define NHT (HH/TH)              // 12 strips per slice
#define ABLOCKS (BB*DD*NHT)      // 3840
#define ATHREADS 640
#define PADW 161                 // padded row stride (bank-conflict-free)

#define S_SIZE (5*HALO_R*WW)     // 19200 floats (stats; reused as OUT)
#define HS_SIZE (5*TH*PADW)      // 12880 floats (H-summed)
#define SMEM_BYTES ((S_SIZE + HS_SIZE)*4)   // 128,320 B

// ---------------- Kernel B tiling ----------------
#define SEG_D 8
#define SEGLEN (DD/SEG_D)        // 20
#define VCOLS (BB*HW/4)          // 15360 float4 columns
#define BTHREADS 256
#define BBLOCKS (VCOLS*SEG_D/BTHREADS)  // 480

// 5-channel HW-box-summed stats (written once by A, read once by B). ~196MB.
__device__ float g_stats[5ULL * NVOX];
__device__ double g_part[BBLOCKS];
__device__ int g_sem;   // self-resetting semaphore (0 at start of every launch)

// ===========================================================================
// Kernel A: per (b,d) slice, strip of TH output rows x full W.
// Computes 5 stats, H box-sum (rolling), W box-sum (rolling), writes to g_stats.
// ===========================================================================
__global__ __launch_bounds__(ATHREADS) void boxHW_kernel(
    const float* __restrict__ I, const float* __restrict__ J) {
    extern __shared__ float sm[];
    float* S   = sm;             // [5][HALO_R][WW]
    float* HS  = sm + S_SIZE;    // [5][TH][PADW]
    float* OUT = sm;             // aliases S (dead after P2)

    int blk = blockIdx.x;
    int ht  = blk % NHT;
    int bd  = blk / NHT;                  // b*DD + d
    int h0  = ht * TH;
    const int slice_base = bd * HW;       // (b,d,0,0)
    int tid = threadIdx.x;

    // P1: load input halo rows, compute 5 stats into shared.
    for (int idx = tid; idx < HALO_R * WW; idx += ATHREADS) {
        int r = idx / WW, w = idx % WW;
        int h = h0 - 4 + r;
        float i = 0.f, j = 0.f;
        if (h >= 0 && h < HH) {
            int g = slice_base + h * WW + w;
            i = I[g]; j = J[g];
        }
        S[0*HALO_R*WW + idx] = i;
        S[1*HALO_R*WW + idx] = j;
        S[2*HALO_R*WW + idx] = i * i;
        S[3*HALO_R*WW + idx] = j * j;
        S[4*HALO_R*WW + idx] = i * j;
    }
    __syncthreads();

    // P2: H box-sum, per-thread rolling along h. Tasks = 5*WW = 800.
    for (int t = tid; t < 5 * WW; t += ATHREADS) {
        int w = t % WW, c = t / WW;
        const float* Sc = S + c * HALO_R * WW;
        float* Hc = HS + c * TH * PADW;
        float s = 0.f;
        #pragma unroll
        for (int r = 0; r < 8; ++r) s += Sc[r * WW + w];
        #pragma unroll
        for (int ro = 0; ro < TH; ++ro) {
            s += Sc[(ro + 8) * WW + w];     // window rows [ro, ro+8]
            Hc[ro * PADW + w] = s;
            s -= Sc[ro * WW + w];
        }
    }
    __syncthreads();

    // P3: W box-sum, per-thread rolling along w in chunks of 20.
    // Tasks = 5 * TH * 8 = 640 == ATHREADS exactly.
    {
        int t = tid;
        int k    = t % 8;
        int rest = t / 8;
        int ho   = rest % TH;
        int c    = rest / TH;
        const float* Hr = HS  + (c * TH + ho) * PADW;
        float*       Or = OUT + (c * TH + ho) * PADW;
        int wbase = k * 20;
        float s = 0.f;
        #pragma unroll
        for (int x = wbase - 4; x < wbase + 4; ++x)
            if (x >= 0) s += Hr[x];          // x <= 143 < WW always
        #pragma unroll
        for (int wo = wbase; wo < wbase + 20; ++wo) {
            int xa = wo + 4;
            if (xa < WW) s += Hr[xa];
            Or[wo] = s;
            int xs = wo - 4;
            if (xs >= 0) s -= Hr[xs];
        }
    }
    __syncthreads();

    // Coalesced copy OUT(shared, padded) -> g_stats(global).
    for (int idx = tid; idx < 5 * TH * WW; idx += ATHREADS) {
        int w    = idx % WW;
        int rest = idx / WW;
        int ho   = rest % TH;
        int c    = rest / TH;
        g_stats[(size_t)c * NVOX + slice_base + (h0 + ho) * WW + w] =
            OUT[(c * TH + ho) * PADW + w];
    }
}

// ===========================================================================
// Kernel B: rolling D box-sum per float4 column + cc math + full reduction.
// Last block folds partials into the output scalar (semaphore, self-reset).
// ===========================================================================
__device__ __forceinline__ float cc1(float s0, float s1, float s2, float s3,
                                     float s4) {
    float cross = fmaf(-s0 * INV_WIN3, s1, s4);   // IJ - I*J/N
    float Ivar  = fmaf(-s0 * INV_WIN3, s0, s2);
    float Jvar  = fmaf(-s1 * INV_WIN3, s1, s3);
    return __fdividef(cross * cross, fmaf(Ivar, Jvar, 1e-5f));
}

__global__ __launch_bounds__(BTHREADS) void dsum_cc_kernel(float* __restrict__ out) {
    int gtid = blockIdx.x * BTHREADS + threadIdx.x;
    int vcol = gtid % VCOLS;
    int seg  = gtid / VCOLS;
    int b    = vcol / (HW / 4);
    int hw   = (vcol % (HW / 4)) * 4;
    const size_t base = (size_t)b * DHW + hw;
    int d0 = seg * SEGLEN;

    float4 s[5];
    #pragma unroll
    for (int c = 0; c < 5; ++c) s[c] = make_float4(0.f, 0.f, 0.f, 0.f);

    int dstart = d0 - 4 > 0 ? d0 - 4 : 0;
    for (int d = dstart; d < d0 + 4; ++d) {
        size_t o = base + (size_t)d * HW;
        #pragma unroll
        for (int c = 0; c < 5; ++c) {
            float4 v = *(const float4*)&g_stats[(size_t)c * NVOX + o];
            s[c].x += v.x; s[c].y += v.y; s[c].z += v.z; s[c].w += v.w;
        }
    }

    float acc = 0.f;
    for (int dd = d0; dd < d0 + SEGLEN; ++dd) {
        int da = dd + 4;
        if (da < DD) {
            size_t o = base + (size_t)da * HW;
            #pragma unroll
            for (int c = 0; c < 5; ++c) {
                float4 v = *(const float4*)&g_stats[(size_t)c * NVOX + o];
                s[c].x += v.x; s[c].y += v.y; s[c].z += v.z; s[c].w += v.w;
            }
        }
        acc += cc1(s[0].x, s[1].x, s[2].x, s[3].x, s[4].x);
        acc += cc1(s[0].y, s[1].y, s[2].y, s[3].y, s[4].y);
        acc += cc1(s[0].z, s[1].z, s[2].z, s[3].z, s[4].z);
        acc += cc1(s[0].w, s[1].w, s[2].w, s[3].w, s[4].w);
        int ds = dd - 4;
        if (ds >= 0) {
            size_t o = base + (size_t)ds * HW;   // L1/L2 hit (read 8 iters ago)
            #pragma unroll
            for (int c = 0; c < 5; ++c) {
                float4 v = *(const float4*)&g_stats[(size_t)c * NVOX + o];
                s[c].x -= v.x; s[c].y -= v.y; s[c].z -= v.z; s[c].w -= v.w;
            }
        }
    }

    // Block reduction (float within warp, double across warps).
    __shared__ double wsum[BTHREADS / 32];
    #pragma unroll
    for (int off = 16; off; off >>= 1)
        acc += __shfl_down_sync(0xffffffffu, acc, off);
    int lane = threadIdx.x & 31, wid = threadIdx.x >> 5;
    if (lane == 0) wsum[wid] = (double)acc;
    __syncthreads();

    __shared__ bool is_last;
    if (threadIdx.x == 0) {
        double t = 0.0;
        #pragma unroll
        for (int i = 0; i < BTHREADS / 32; ++i) t += wsum[i];
        g_part[blockIdx.x] = t;
        __threadfence();
        int v = atomicAdd(&g_sem, 1);
        is_last = (v == gridDim.x - 1);
    }
    __syncthreads();

    if (is_last) {
        __threadfence();
        double t = 0.0;
        for (int i = threadIdx.x; i < BBLOCKS; i += BTHREADS) t += g_part[i];
        #pragma unroll
        for (int off = 16; off; off >>= 1)
            t += __shfl_down_sync(0xffffffffu, t, off);
        __shared__ double fsum[BTHREADS / 32];
        if (lane == 0) fsum[wid] = t;
        __syncthreads();
        if (threadIdx.x == 0) {
            double tot = 0.0;
            #pragma unroll
            for (int i = 0; i < BTHREADS / 32; ++i) tot += fsum[i];
            out[0] = (float)(tot / (double)NVOX);
            g_sem = 0;   // reset for next graph replay
        }
    }
}

extern "C" void kernel_launch(void* const* d_in, const int* in_sizes, int n_in,
                              void* d_out, int out_size) {
    const float* I = (const float*)d_in[0];  // predicted
    const float* J = (const float*)d_in[1];  // target

    cudaFuncSetAttribute(boxHW_kernel,
                         cudaFuncAttributeMaxDynamicSharedMemorySize, SMEM_BYTES);

    boxHW_kernel<<<ABLOCKS, ATHREADS, SMEM_BYTES>>>(I, J);
    dsum_cc_kernel<<<BBLOCKS, BTHREADS>>>((float*)d_out);
}

// round 3
// speedup vs baseline: 2.3456x; 1.5918x over previous
#include <cuda_runtime.h>

#define BB 2
#define DD 160
#define HH 192
#define WW 160
#define HW (HH*WW)               // 30720
#define DHW (DD*HH*WW)           // 4,915,200
#define NVOX (BB*DD*HH*WW)       // 9,830,400
#define INV_WIN3 (1.0f/729.0f)

// ---------------- K1: stats + H box-sum (rolling, streaming) ----------------
#define SEG_H1 8
#define SEGLEN_H1 (HH/SEG_H1)    // 24
#define COLS4 (BB*DD*WW/4)       // 12800 float4 columns
#define K1_THREADS (COLS4*SEG_H1)  // 102400
#define K1_BLK 256

// ---------------- K2: D-roll + W-roll + cc + reduce ----------------
#define ROWS2 4
#define SEG_D2 8
#define SEGLEN_D2 (DD/SEG_D2)    // 20
#define HTILES (HH/ROWS2)        // 48
#define K2_BLOCKS (BB*HTILES*SEG_D2)   // 768
#define K2_THREADS 160           // 4 rows x 40 float4-lanes
#define SMROW 42                 // float4s per padded row (1 pad + 40 + 1 pad)

// H-summed 5-channel stats, written once by K1, read by K2. ~196 MB.
__device__ float g_buf[5ULL * NVOX];
__device__ double g_part[K2_BLOCKS];
__device__ int g_sem;            // self-resetting (0 at start of every replay)

// ===========================================================================
// K1: thread = float4 column; compute 5 stats on the fly, roll along H.
// ===========================================================================
__global__ __launch_bounds__(K1_BLK) void stats_h_kernel(
    const float* __restrict__ I, const float* __restrict__ J) {
    int tid = blockIdx.x * K1_BLK + threadIdx.x;
    if (tid >= K1_THREADS) return;
    int col4 = tid % COLS4;
    int seg  = tid / COLS4;
    int b    = col4 / (DD * WW / 4);
    int rest = col4 % (DD * WW / 4);
    int d    = rest / (WW / 4);
    int w4   = rest % (WW / 4);
    const size_t base = (size_t)b * DHW + (size_t)d * HW + (size_t)w4 * 4;
    int h0 = seg * SEGLEN_H1;

    float4 s0 = {0,0,0,0}, s1 = s0, s2 = s0, s3 = s0, s4 = s0;

    int hp = h0 - 4 > 0 ? h0 - 4 : 0;
    for (int h = hp; h < h0 + 4; ++h) {
        float4 i = *(const float4*)&I[base + (size_t)h * WW];
        float4 j = *(const float4*)&J[base + (size_t)h * WW];
        s0.x+=i.x; s0.y+=i.y; s0.z+=i.z; s0.w+=i.w;
        s1.x+=j.x; s1.y+=j.y; s1.z+=j.z; s1.w+=j.w;
        s2.x+=i.x*i.x; s2.y+=i.y*i.y; s2.z+=i.z*i.z; s2.w+=i.w*i.w;
        s3.x+=j.x*j.x; s3.y+=j.y*j.y; s3.z+=j.z*j.z; s3.w+=j.w*j.w;
        s4.x+=i.x*j.x; s4.y+=i.y*j.y; s4.z+=i.z*j.z; s4.w+=i.w*j.w;
    }

    for (int ho = h0; ho < h0 + SEGLEN_H1; ++ho) {
        int ha = ho + 4;
        if (ha < HH) {
            float4 i = *(const float4*)&I[base + (size_t)ha * WW];
            float4 j = *(const float4*)&J[base + (size_t)ha * WW];
            s0.x+=i.x; s0.y+=i.y; s0.z+=i.z; s0.w+=i.w;
            s1.x+=j.x; s1.y+=j.y; s1.z+=j.z; s1.w+=j.w;
            s2.x+=i.x*i.x; s2.y+=i.y*i.y; s2.z+=i.z*i.z; s2.w+=i.w*i.w;
            s3.x+=j.x*j.x; s3.y+=j.y*j.y; s3.z+=j.z*j.z; s3.w+=j.w*j.w;
            s4.x+=i.x*j.x; s4.y+=i.y*j.y; s4.z+=i.z*j.z; s4.w+=i.w*j.w;
        }
        size_t o = base + (size_t)ho * WW;
        *(float4*)&g_buf[0ULL*NVOX + o] = s0;
        *(float4*)&g_buf[1ULL*NVOX + o] = s1;
        *(float4*)&g_buf[2ULL*NVOX + o] = s2;
        *(float4*)&g_buf[3ULL*NVOX + o] = s3;
        *(float4*)&g_buf[4ULL*NVOX + o] = s4;
        int hs = ho - 4;
        if (hs >= 0) {
            float4 i = *(const float4*)&I[base + (size_t)hs * WW];  // L1 hit
            float4 j = *(const float4*)&J[base + (size_t)hs * WW];
            s0.x-=i.x; s0.y-=i.y; s0.z-=i.z; s0.w-=i.w;
            s1.x-=j.x; s1.y-=j.y; s1.z-=j.z; s1.w-=j.w;
            s2.x-=i.x*i.x; s2.y-=i.y*i.y; s2.z-=i.z*i.z; s2.w-=i.w*i.w;
            s3.x-=j.x*j.x; s3.y-=j.y*j.y; s3.z-=j.z*j.z; s3.w-=j.w*j.w;
            s4.x-=i.x*j.x; s4.y-=i.y*j.y; s4.z-=i.z*j.z; s4.w-=i.w*j.w;
        }
    }
}

// ===========================================================================
// K2: rolling D box-sum per float4 column; per d-step stage accums into a
// padded smem row tile, compute 9-wide W windows + cc; global reduction.
// ===========================================================================
__device__ __forceinline__ float cc1(float s0, float s1, float s2, float s3,
                                     float s4) {
    float cross = fmaf(-s0 * INV_WIN3, s1, s4);
    float Ivar  = fmaf(-s0 * INV_WIN3, s0, s2);
    float Jvar  = fmaf(-s1 * INV_WIN3, s1, s3);
    return __fdividef(cross * cross, fmaf(Ivar, Jvar, 1e-5f));
}

__global__ __launch_bounds__(K2_THREADS) void dwc_kernel(float* __restrict__ out) {
    __shared__ float4 sm[5 * ROWS2 * SMROW];   // 13,440 B
    __shared__ double wsum[K2_THREADS / 32];
    __shared__ bool is_last;

    int bx   = blockIdx.x;
    int dseg = bx % SEG_D2;
    int rest = bx / SEG_D2;
    int htile = rest % HTILES;
    int b     = rest / HTILES;
    int h0 = htile * ROWS2;
    int tid = threadIdx.x;
    int r  = tid / 40;
    int wi = tid % 40;

    // zero smem (pads included)
    for (int i = tid; i < 5 * ROWS2 * SMROW; i += K2_THREADS)
        sm[i] = make_float4(0.f, 0.f, 0.f, 0.f);

    const size_t colbase = (size_t)b * DHW + (size_t)(h0 + r) * WW + wi * 4;
    int d0 = dseg * SEGLEN_D2;

    float4 s[5];
    #pragma unroll
    for (int c = 0; c < 5; ++c) s[c] = make_float4(0.f, 0.f, 0.f, 0.f);

    int dp = d0 - 4 > 0 ? d0 - 4 : 0;
    for (int d = dp; d < d0 + 4; ++d) {
        size_t o = colbase + (size_t)d * HW;
        #pragma unroll
        for (int c = 0; c < 5; ++c) {
            float4 v = *(const float4*)&g_buf[(size_t)c * NVOX + o];
            s[c].x+=v.x; s[c].y+=v.y; s[c].z+=v.z; s[c].w+=v.w;
        }
    }
    __syncthreads();   // pads zeroed before first stage

    float acc = 0.f;
    for (int dd = d0; dd < d0 + SEGLEN_D2; ++dd) {
        int da = dd + 4;
        if (da < DD) {
            size_t o = colbase + (size_t)da * HW;
            #pragma unroll
            for (int c = 0; c < 5; ++c) {
                float4 v = *(const float4*)&g_buf[(size_t)c * NVOX + o];
                s[c].x+=v.x; s[c].y+=v.y; s[c].z+=v.z; s[c].w+=v.w;
            }
        }
        // stage accums: row base (c*ROWS2 + r)*SMROW, data at f4 idx 1+wi
        #pragma unroll
        for (int c = 0; c < 5; ++c)
            sm[(c * ROWS2 + r) * SMROW + 1 + wi] = s[c];
        __syncthreads();

        // W windows: outputs w=4wi..4wi+3 need floats 4wi-4 .. 4wi+11
        float win[5][4];
        #pragma unroll
        for (int c = 0; c < 5; ++c) {
            int rb = (c * ROWS2 + r) * SMROW + wi;  // f4 idx wi,wi+1,wi+2
            float4 a0 = sm[rb], a1 = sm[rb + 1], a2 = sm[rb + 2];
            float f0=a0.x,f1=a0.y,f2=a0.z,f3=a0.w;
            float f4_=a1.x,f5=a1.y,f6=a1.z,f7=a1.w;
            float f8=a2.x,f9=a2.y,f10=a2.z,f11=a2.w;
            float t = f0+f1+f2+f3+f4_+f5+f6+f7+f8;
            win[c][0] = t;
            t += f9  - f0; win[c][1] = t;
            t += f10 - f1; win[c][2] = t;
            t += f11 - f2; win[c][3] = t;
        }
        #pragma unroll
        for (int k = 0; k < 4; ++k)
            acc += cc1(win[0][k], win[1][k], win[2][k], win[3][k], win[4][k]);
        __syncthreads();

        int ds = dd - 4;
        if (ds >= 0) {
            size_t o = colbase + (size_t)ds * HW;   // L2 hit (8 steps back)
            #pragma unroll
            for (int c = 0; c < 5; ++c) {
                float4 v = *(const float4*)&g_buf[(size_t)c * NVOX + o];
                s[c].x-=v.x; s[c].y-=v.y; s[c].z-=v.z; s[c].w-=v.w;
            }
        }
    }

    // block reduction: 5 warps
    #pragma unroll
    for (int off = 16; off; off >>= 1)
        acc += __shfl_down_sync(0xffffffffu, acc, off);
    int lane = tid & 31, wid = tid >> 5;
    if (lane == 0) wsum[wid] = (double)acc;
    __syncthreads();

    if (tid == 0) {
        double t = 0.0;
        #pragma unroll
        for (int i = 0; i < K2_THREADS / 32; ++i) t += wsum[i];
        g_part[bx] = t;
        __threadfence();
        int v = atomicAdd(&g_sem, 1);
        is_last = (v == gridDim.x - 1);
    }
    __syncthreads();

    if (is_last) {
        __threadfence();
        double t = 0.0;
        for (int i = tid; i < K2_BLOCKS; i += K2_THREADS) t += g_part[i];
        #pragma unroll
        for (int off = 16; off; off >>= 1)
            t += __shfl_down_sync(0xffffffffu, t, off);
        if (lane == 0) wsum[wid] = t;
        __syncthreads();
        if (tid == 0) {
            double tot = 0.0;
            #pragma unroll
            for (int i = 0; i < K2_THREADS / 32; ++i) tot += wsum[i];
            out[0] = (float)(tot / (double)NVOX);
            g_sem = 0;   // reset for next graph replay
        }
    }
}

extern "C" void kernel_launch(void* const* d_in, const int* in_sizes, int n_in,
                              void* d_out, int out_size) {
    const float* I = (const float*)d_in[0];  // predicted
    const float* J = (const float*)d_in[1];  // target

    stats_h_kernel<<<(K1_THREADS + K1_BLK - 1) / K1_BLK, K1_BLK>>>(I, J);
    dwc_kernel<<<K2_BLOCKS, K2_THREADS>>>((float*)d_out);
}

// round 4
// speedup vs baseline: 2.5725x; 1.0967x over previous
#include <cuda_runtime.h>

#define BB 2
#define DD 160
#define HH 192
#define WW 160
#define HW (HH*WW)               // 30720
#define DHW (DD*HH*WW)           // 4,915,200
#define NVOX (BB*DD*HH*WW)       // 9,830,400
#define INV_WIN3 (1.0f/729.0f)

// ---------------- K1: stats + H box-sum (register ring, streaming) ----------
#define SEG_H1 8
#define SEGLEN_H1 (HH/SEG_H1)    // 24 (multiple of 8 -> compile-time ring slots)
#define COLS4 (BB*DD*WW/4)       // 12800 float4 columns
#define K1_THREADS (COLS4*SEG_H1)  // 102400
#define K1_BLK 256

// ---------------- K2: D-roll + W-roll + cc + reduce ----------------
#define ROWS2 4
#define SEG_D2 5
#define SEGLEN_D2 (DD/SEG_D2)    // 32
#define HTILES (HH/ROWS2)        // 48
#define K2_BLOCKS (BB*HTILES*SEG_D2)   // 480
#define K2_THREADS 160           // 4 rows x 40 float4-lanes
#define SMROW 42                 // float4s per padded row (1 pad + 40 + 1 pad)

// H-summed 5-channel stats, written once by K1, read by K2. ~196 MB.
__device__ float g_buf[5ULL * NVOX];
__device__ double g_part[K2_BLOCKS];
__device__ int g_sem;            // self-resetting (0 at start of every replay)

__device__ __forceinline__ void acc_add(float4 s[5], float4 i, float4 j) {
    s[0].x+=i.x; s[0].y+=i.y; s[0].z+=i.z; s[0].w+=i.w;
    s[1].x+=j.x; s[1].y+=j.y; s[1].z+=j.z; s[1].w+=j.w;
    s[2].x+=i.x*i.x; s[2].y+=i.y*i.y; s[2].z+=i.z*i.z; s[2].w+=i.w*i.w;
    s[3].x+=j.x*j.x; s[3].y+=j.y*j.y; s[3].z+=j.z*j.z; s[3].w+=j.w*j.w;
    s[4].x+=i.x*j.x; s[4].y+=i.y*j.y; s[4].z+=i.z*j.z; s[4].w+=i.w*j.w;
}
__device__ __forceinline__ void acc_sub(float4 s[5], float4 i, float4 j) {
    s[0].x-=i.x; s[0].y-=i.y; s[0].z-=i.z; s[0].w-=i.w;
    s[1].x-=j.x; s[1].y-=j.y; s[1].z-=j.z; s[1].w-=j.w;
    s[2].x-=i.x*i.x; s[2].y-=i.y*i.y; s[2].z-=i.z*i.z; s[2].w-=i.w*i.w;
    s[3].x-=j.x*j.x; s[3].y-=j.y*j.y; s[3].z-=j.z*j.z; s[3].w-=j.w*j.w;
    s[4].x-=i.x*j.x; s[4].y-=i.y*j.y; s[4].z-=i.z*j.z; s[4].w-=i.w*j.w;
}

// ===========================================================================
// K1: thread = float4 column; 8-deep register ring of raw I,J rows; roll H.
// No redundant global reads: each input read once, each output written once.
// ===========================================================================
__global__ __launch_bounds__(K1_BLK) void stats_h_kernel(
    const float* __restrict__ I, const float* __restrict__ J) {
    int tid = blockIdx.x * K1_BLK + threadIdx.x;
    if (tid >= K1_THREADS) return;
    int col4 = tid % COLS4;
    int seg  = tid / COLS4;
    int b    = col4 / (DD * WW / 4);
    int rest = col4 % (DD * WW / 4);
    int d    = rest / (WW / 4);
    int w4   = rest % (WW / 4);
    const size_t base = (size_t)b * DHW + (size_t)d * HW + (size_t)w4 * 4;
    const int h0 = seg * SEGLEN_H1;   // multiple of 8

    float4 ringI[8], ringJ[8];
    float4 s[5];
    #pragma unroll
    for (int c = 0; c < 5; ++c) s[c] = make_float4(0.f,0.f,0.f,0.f);

    // Prime rows h0-4 .. h0+3 into slots (k+4)&7, accumulate stats.
    #pragma unroll
    for (int k = 0; k < 8; ++k) {
        int h = h0 - 4 + k;
        float4 i = make_float4(0.f,0.f,0.f,0.f), j = i;
        if (h >= 0 && h < HH) {
            i = __ldcs((const float4*)&I[base + (size_t)h * WW]);
            j = __ldcs((const float4*)&J[base + (size_t)h * WW]);
        }
        ringI[(k + 4) & 7] = i;
        ringJ[(k + 4) & 7] = j;
        acc_add(s, i, j);
    }

    for (int hb = h0; hb < h0 + SEGLEN_H1; hb += 8) {
        #pragma unroll
        for (int u = 0; u < 8; ++u) {
            const int slot = (u + 4) & 7;     // == (hb+u+4)&7 since hb%8==0
            int h  = hb + u;
            int ha = h + 4;
            float4 oi = ringI[slot], oj = ringJ[slot];
            float4 ni = make_float4(0.f,0.f,0.f,0.f), nj = ni;
            if (ha < HH) {
                ni = __ldcs((const float4*)&I[base + (size_t)ha * WW]);
                nj = __ldcs((const float4*)&J[base + (size_t)ha * WW]);
            }
            ringI[slot] = ni; ringJ[slot] = nj;
            acc_add(s, ni, nj);               // window now [h-4, h+4]
            size_t o = base + (size_t)h * WW;
            __stcs((float4*)&g_buf[0ULL*NVOX + o], s[0]);
            __stcs((float4*)&g_buf[1ULL*NVOX + o], s[1]);
            __stcs((float4*)&g_buf[2ULL*NVOX + o], s[2]);
            __stcs((float4*)&g_buf[3ULL*NVOX + o], s[3]);
            __stcs((float4*)&g_buf[4ULL*NVOX + o], s[4]);
            acc_sub(s, oi, oj);               // drop row h-4
        }
    }
}

// ===========================================================================
// K2: rolling D box-sum per float4 column; per d-step stage accums into a
// padded smem row tile, compute 9-wide W windows + cc; global reduction.
// Adds: __ldcg (L2-resident for the 8-step lag). Subs: __ldcs (dead after).
// ===========================================================================
__device__ __forceinline__ float cc1(float s0, float s1, float s2, float s3,
                                     float s4) {
    float cross = fmaf(-s0 * INV_WIN3, s1, s4);
    float Ivar  = fmaf(-s0 * INV_WIN3, s0, s2);
    float Jvar  = fmaf(-s1 * INV_WIN3, s1, s3);
    return __fdividef(cross * cross, fmaf(Ivar, Jvar, 1e-5f));
}

__global__ __launch_bounds__(K2_THREADS) void dwc_kernel(float* __restrict__ out) {
    __shared__ float4 sm[5 * ROWS2 * SMROW];   // 13,440 B
    __shared__ double wsum[K2_THREADS / 32];
    __shared__ bool is_last;

    int bx   = blockIdx.x;
    int dseg = bx % SEG_D2;
    int rest = bx / SEG_D2;
    int htile = rest % HTILES;
    int b     = rest / HTILES;
    int h0 = htile * ROWS2;
    int tid = threadIdx.x;
    int r  = tid / 40;
    int wi = tid % 40;

    for (int i = tid; i < 5 * ROWS2 * SMROW; i += K2_THREADS)
        sm[i] = make_float4(0.f, 0.f, 0.f, 0.f);

    const size_t colbase = (size_t)b * DHW + (size_t)(h0 + r) * WW + wi * 4;
    int d0 = dseg * SEGLEN_D2;

    float4 s[5];
    #pragma unroll
    for (int c = 0; c < 5; ++c) s[c] = make_float4(0.f, 0.f, 0.f, 0.f);

    int dp = d0 - 4 > 0 ? d0 - 4 : 0;
    for (int d = dp; d < d0 + 4; ++d) {
        size_t o = colbase + (size_t)d * HW;
        #pragma unroll
        for (int c = 0; c < 5; ++c) {
            float4 v = __ldcg((const float4*)&g_buf[(size_t)c * NVOX + o]);
            s[c].x+=v.x; s[c].y+=v.y; s[c].z+=v.z; s[c].w+=v.w;
        }
    }
    __syncthreads();   // pads zeroed before first stage

    float acc = 0.f;
    for (int dd = d0; dd < d0 + SEGLEN_D2; ++dd) {
        int da = dd + 4;
        if (da < DD) {
            size_t o = colbase + (size_t)da * HW;
            #pragma unroll
            for (int c = 0; c < 5; ++c) {
                float4 v = __ldcg((const float4*)&g_buf[(size_t)c * NVOX + o]);
                s[c].x+=v.x; s[c].y+=v.y; s[c].z+=v.z; s[c].w+=v.w;
            }
        }
        #pragma unroll
        for (int c = 0; c < 5; ++c)
            sm[(c * ROWS2 + r) * SMROW + 1 + wi] = s[c];
        __syncthreads();

        float win[5][4];
        #pragma unroll
        for (int c = 0; c < 5; ++c) {
            int rb = (c * ROWS2 + r) * SMROW + wi;
            float4 a0 = sm[rb], a1 = sm[rb + 1], a2 = sm[rb + 2];
            float f0=a0.x,f1=a0.y,f2=a0.z,f3=a0.w;
            float f4_=a1.x,f5=a1.y,f6=a1.z,f7=a1.w;
            float f8=a2.x,f9=a2.y,f10=a2.z,f11=a2.w;
            float t = f0+f1+f2+f3+f4_+f5+f6+f7+f8;
            win[c][0] = t;
            t += f9  - f0; win[c][1] = t;
            t += f10 - f1; win[c][2] = t;
            t += f11 - f2; win[c][3] = t;
        }
        #pragma unroll
        for (int k = 0; k < 4; ++k)
            acc += cc1(win[0][k], win[1][k], win[2][k], win[3][k], win[4][k]);
        __syncthreads();

        int ds = dd - 4;
        if (ds >= 0) {
            size_t o = colbase + (size_t)ds * HW;   // L2 hit; dead after this
            #pragma unroll
            for (int c = 0; c < 5; ++c) {
                float4 v = __ldcs((const float4*)&g_buf[(size_t)c * NVOX + o]);
                s[c].x-=v.x; s[c].y-=v.y; s[c].z-=v.z; s[c].w-=v.w;
            }
        }
    }

    #pragma unroll
    for (int off = 16; off; off >>= 1)
        acc += __shfl_down_sync(0xffffffffu, acc, off);
    int lane = tid & 31, wid = tid >> 5;
    if (lane == 0) wsum[wid] = (double)acc;
    __syncthreads();

    if (tid == 0) {
        double t = 0.0;
        #pragma unroll
        for (int i = 0; i < K2_THREADS / 32; ++i) t += wsum[i];
        g_part[bx] = t;
        __threadfence();
        int v = atomicAdd(&g_sem, 1);
        is_last = (v == gridDim.x - 1);
    }
    __syncthreads();

    if (is_last) {
        __threadfence();
        double t = 0.0;
        for (int i = tid; i < K2_BLOCKS; i += K2_THREADS) t += g_part[i];
        #pragma unroll
        for (int off = 16; off; off >>= 1)
            t += __shfl_down_sync(0xffffffffu, t, off);
        if (lane == 0) wsum[wid] = t;
        __syncthreads();
        if (tid == 0) {
            double tot = 0.0;
            #pragma unroll
            for (int i = 0; i < K2_THREADS / 32; ++i) tot += wsum[i];
            out[0] = (float)(tot / (double)NVOX);
            g_sem = 0;   // reset for next graph replay
        }
    }
}

extern "C" void kernel_launch(void* const* d_in, const int* in_sizes, int n_in,
                              void* d_out, int out_size) {
    const float* I = (const float*)d_in[0];  // predicted
    const float* J = (const float*)d_in[1];  // target

    stats_h_kernel<<<(K1_THREADS + K1_BLK - 1) / K1_BLK, K1_BLK>>>(I, J);
    dwc_kernel<<<K2_BLOCKS, K2_THREADS>>>((float*)d_out);
}

// round 6
// speedup vs baseline: 3.1026x; 1.2061x over previous
#include <cuda_runtime.h>
#include <cuda_fp16.h>
#include <cstdint>

#define BB 2
#define DD 160
#define HH 192
#define WW 160
#define HW (HH*WW)               // 30720
#define DHW (DD*HH*WW)           // 4,915,200
#define NVOX (BB*DD*HH*WW)       // 9,830,400
#define NV4 (NVOX/4)             // 2,457,600
#define INV_WIN3 (1.0f/729.0f)

// ---------------- K1: stats + H box-sum (register ring, streaming) ----------
#define SEG_H1 8
#define SEGLEN_H1 (HH/SEG_H1)    // 24 (multiple of 8 -> compile-time ring slots)
#define COLS4 (BB*DD*WW/4)       // 12800 float4 columns
#define K1_THREADS (COLS4*SEG_H1)  // 102400
#define K1_BLK 256

// ---------------- K2: D-roll + W-roll + cc + reduce ----------------
#define ROWS2 4
#define SEG_D2 8
#define SEGLEN_D2 (DD/SEG_D2)    // 20
#define HTILES (HH/ROWS2)        // 48
#define K2_BLOCKS (BB*HTILES*SEG_D2)   // 768
#define K2_THREADS 160           // 4 rows x 40 float4-lanes
#define SMROW 42                 // float4s per padded row (1 pad + 40 + 1 pad)

// Packed fp16 H-summed stats (written once by K1, read by K2). ~98 MB total.
__device__ uint4 g_ab[NV4];      // ch0(I),  ch1(J)   : 8 halves
__device__ uint4 g_cd[NV4];      // ch2(I2), ch3(J2)  : 8 halves
__device__ uint2 g_e [NV4];      // ch4(IJ)           : 4 halves
__device__ double g_part[K2_BLOCKS];
__device__ int g_sem;            // self-resetting (0 at start of every replay)

__device__ __forceinline__ unsigned int pack2(float a, float b) {
    __half2 h = __floats2half2_rn(a, b);
    return *(unsigned int*)&h;
}
__device__ __forceinline__ float2 unpack2(unsigned int u) {
    __half2 h = *(__half2*)&u;
    return __half22float2(h);
}

__device__ __forceinline__ void acc_add(float4 s[5], float4 i, float4 j) {
    s[0].x+=i.x; s[0].y+=i.y; s[0].z+=i.z; s[0].w+=i.w;
    s[1].x+=j.x; s[1].y+=j.y; s[1].z+=j.z; s[1].w+=j.w;
    s[2].x+=i.x*i.x; s[2].y+=i.y*i.y; s[2].z+=i.z*i.z; s[2].w+=i.w*i.w;
    s[3].x+=j.x*j.x; s[3].y+=j.y*j.y; s[3].z+=j.z*j.z; s[3].w+=j.w*j.w;
    s[4].x+=i.x*j.x; s[4].y+=i.y*j.y; s[4].z+=i.z*j.z; s[4].w+=i.w*j.w;
}
__device__ __forceinline__ void acc_sub(float4 s[5], float4 i, float4 j) {
    s[0].x-=i.x; s[0].y-=i.y; s[0].z-=i.z; s[0].w-=i.w;
    s[1].x-=j.x; s[1].y-=j.y; s[1].z-=j.z; s[1].w-=j.w;
    s[2].x-=i.x*i.x; s[2].y-=i.y*i.y; s[2].z-=i.z*i.z; s[2].w-=i.w*i.w;
    s[3].x-=j.x*j.x; s[3].y-=j.y*j.y; s[3].z-=j.z*j.z; s[3].w-=j.w*j.w;
    s[4].x-=i.x*j.x; s[4].y-=i.y*j.y; s[4].z-=i.z*j.z; s[4].w-=i.w*j.w;
}

// ===========================================================================
// K1: thread = float4 column; 8-deep register ring of raw I,J rows; roll H.
// Outputs packed fp16 channel pairs.
// ===========================================================================
__global__ __launch_bounds__(K1_BLK) void stats_h_kernel(
    const float* __restrict__ I, const float* __restrict__ J) {
    int tid = blockIdx.x * K1_BLK + threadIdx.x;
    if (tid >= K1_THREADS) return;
    int col4 = tid % COLS4;
    int seg  = tid / COLS4;
    int b    = col4 / (DD * WW / 4);
    int rest = col4 % (DD * WW / 4);
    int d    = rest / (WW / 4);
    int w4   = rest % (WW / 4);
    const size_t base = (size_t)b * DHW + (size_t)d * HW + (size_t)w4 * 4;
    const int h0 = seg * SEGLEN_H1;   // multiple of 8

    float4 ringI[8], ringJ[8];
    float4 s[5];
    #pragma unroll
    for (int c = 0; c < 5; ++c) s[c] = make_float4(0.f,0.f,0.f,0.f);

    #pragma unroll
    for (int k = 0; k < 8; ++k) {
        int h = h0 - 4 + k;
        float4 i = make_float4(0.f,0.f,0.f,0.f), j = i;
        if (h >= 0 && h < HH) {
            i = __ldcs((const float4*)&I[base + (size_t)h * WW]);
            j = __ldcs((const float4*)&J[base + (size_t)h * WW]);
        }
        ringI[(k + 4) & 7] = i;
        ringJ[(k + 4) & 7] = j;
        acc_add(s, i, j);
    }

    for (int hb = h0; hb < h0 + SEGLEN_H1; hb += 8) {
        #pragma unroll
        for (int u = 0; u < 8; ++u) {
            const int slot = (u + 4) & 7;     // == (hb+u+4)&7 since hb%8==0
            int h  = hb + u;
            int ha = h + 4;
            float4 oi = ringI[slot], oj = ringJ[slot];
            float4 ni = make_float4(0.f,0.f,0.f,0.f), nj = ni;
            if (ha < HH) {
                ni = __ldcs((const float4*)&I[base + (size_t)ha * WW]);
                nj = __ldcs((const float4*)&J[base + (size_t)ha * WW]);
            }
            ringI[slot] = ni; ringJ[slot] = nj;
            acc_add(s, ni, nj);               // window now [h-4, h+4]
            size_t o4 = (base + (size_t)h * WW) >> 2;
            uint4 pab = make_uint4(pack2(s[0].x, s[0].y), pack2(s[0].z, s[0].w),
                                   pack2(s[1].x, s[1].y), pack2(s[1].z, s[1].w));
            uint4 pcd = make_uint4(pack2(s[2].x, s[2].y), pack2(s[2].z, s[2].w),
                                   pack2(s[3].x, s[3].y), pack2(s[3].z, s[3].w));
            uint2 pe  = make_uint2(pack2(s[4].x, s[4].y), pack2(s[4].z, s[4].w));
            __stcs(&g_ab[o4], pab);
            __stcs(&g_cd[o4], pcd);
            __stcs(&g_e [o4], pe);
            acc_sub(s, oi, oj);               // drop row h-4
        }
    }
}

// ===========================================================================
// K2: rolling D box-sum per float4 column (fp16-packed input, fp32 accum);
// per d-step stage into smem, 9-wide W windows + cc; global reduction.
// ===========================================================================
__device__ __forceinline__ float cc1(float s0, float s1, float s2, float s3,
                                     float s4) {
    float cross = fmaf(-s0 * INV_WIN3, s1, s4);
    float Ivar  = fmaf(-s0 * INV_WIN3, s0, s2);
    float Jvar  = fmaf(-s1 * INV_WIN3, s1, s3);
    return __fdividef(cross * cross, fmaf(Ivar, Jvar, 1e-5f));
}

__device__ __forceinline__ void load_add(float4 s[5], size_t o4, float sgn,
                                         bool evict) {
    uint4 vab = evict ? __ldcs(&g_ab[o4]) : __ldcg(&g_ab[o4]);
    uint4 vcd = evict ? __ldcs(&g_cd[o4]) : __ldcg(&g_cd[o4]);
    uint2 ve  = evict ? __ldcs(&g_e [o4]) : __ldcg(&g_e [o4]);
    float2 p;
    p = unpack2(vab.x); s[0].x += sgn*p.x; s[0].y += sgn*p.y;
    p = unpack2(vab.y); s[0].z += sgn*p.x; s[0].w += sgn*p.y;
    p = unpack2(vab.z); s[1].x += sgn*p.x; s[1].y += sgn*p.y;
    p = unpack2(vab.w); s[1].z += sgn*p.x; s[1].w += sgn*p.y;
    p = unpack2(vcd.x); s[2].x += sgn*p.x; s[2].y += sgn*p.y;
    p = unpack2(vcd.y); s[2].z += sgn*p.x; s[2].w += sgn*p.y;
    p = unpack2(vcd.z); s[3].x += sgn*p.x; s[3].y += sgn*p.y;
    p = unpack2(vcd.w); s[3].z += sgn*p.x; s[3].w += sgn*p.y;
    p = unpack2(ve.x);  s[4].x += sgn*p.x; s[4].y += sgn*p.y;
    p = unpack2(ve.y);  s[4].z += sgn*p.x; s[4].w += sgn*p.y;
}

__global__ __launch_bounds__(K2_THREADS) void dwc_kernel(float* __restrict__ out) {
    __shared__ float4 sm[5 * ROWS2 * SMROW];   // 13,440 B
    __shared__ double wsum[K2_THREADS / 32];
    __shared__ bool is_last;

    int bx   = blockIdx.x;
    int dseg = bx % SEG_D2;
    int rest = bx / SEG_D2;
    int htile = rest % HTILES;
    int b     = rest / HTILES;
    int h0 = htile * ROWS2;
    int tid = threadIdx.x;
    int r  = tid / 40;
    int wi = tid % 40;

    for (int i = tid; i < 5 * ROWS2 * SMROW; i += K2_THREADS)
        sm[i] = make_float4(0.f, 0.f, 0.f, 0.f);

    const size_t colbase = (size_t)b * DHW + (size_t)(h0 + r) * WW + wi * 4;
    int d0 = dseg * SEGLEN_D2;

    float4 s[5];
    #pragma unroll
    for (int c = 0; c < 5; ++c) s[c] = make_float4(0.f, 0.f, 0.f, 0.f);

    int dp = d0 - 4 > 0 ? d0 - 4 : 0;
    for (int d = dp; d < d0 + 4; ++d)
        load_add(s, (colbase + (size_t)d * HW) >> 2, 1.f, false);
    __syncthreads();   // pads zeroed before first stage

    float acc = 0.f;
    for (int dd = d0; dd < d0 + SEGLEN_D2; ++dd) {
        int da = dd + 4;
        if (da < DD)
            load_add(s, (colbase + (size_t)da * HW) >> 2, 1.f, false);

        #pragma unroll
        for (int c = 0; c < 5; ++c)
            sm[(c * ROWS2 + r) * SMROW + 1 + wi] = s[c];
        __syncthreads();

        float win[5][4];
        #pragma unroll
        for (int c = 0; c < 5; ++c) {
            int rb = (c * ROWS2 + r) * SMROW + wi;
            float4 a0 = sm[rb], a1 = sm[rb + 1], a2 = sm[rb + 2];
            float f0=a0.x,f1=a0.y,f2=a0.z,f3=a0.w;
            float f4_=a1.x,f5=a1.y,f6=a1.z,f7=a1.w;
            float f8=a2.x,f9=a2.y,f10=a2.z,f11=a2.w;
            float t = f0+f1+f2+f3+f4_+f5+f6+f7+f8;
            win[c][0] = t;
            t += f9  - f0; win[c][1] = t;
            t += f10 - f1; win[c][2] = t;
            t += f11 - f2; win[c][3] = t;
        }
        #pragma unroll
        for (int k = 0; k < 4; ++k)
            acc += cc1(win[0][k], win[1][k], win[2][k], win[3][k], win[4][k]);
        __syncthreads();

        int ds = dd - 4;
        if (ds >= 0)   // L2 hit (8 steps of lag, ~62 MB co-resident); dead after
            load_add(s, (colbase + (size_t)ds * HW) >> 2, -1.f, true);
    }

    #pragma unroll
    for (int off = 16; off; off >>= 1)
        acc += __shfl_down_sync(0xffffffffu, acc, off);
    int lane = tid & 31, wid = tid >> 5;
    if (lane == 0) wsum[wid] = (double)acc;
    __syncthreads();

    if (tid == 0) {
        double t = 0.0;
        #pragma unroll
        for (int i = 0; i < K2_THREADS / 32; ++i) t += wsum[i];
        g_part[bx] = t;
        __threadfence();
        int v = atomicAdd(&g_sem, 1);
        is_last = (v == gridDim.x - 1);
    }
    __syncthreads();

    if (is_last) {
        __threadfence();
        double t = 0.0;
        for (int i = tid; i < K2_BLOCKS; i += K2_THREADS) t += g_part[i];
        #pragma unroll
        for (int off = 16; off; off >>= 1)
            t += __shfl_down_sync(0xffffffffu, t, off);
        if (lane == 0) wsum[wid] = t;
        __syncthreads();
        if (tid == 0) {
            double tot = 0.0;
            #pragma unroll
            for (int i = 0; i < K2_THREADS / 32; ++i) tot += wsum[i];
            out[0] = (float)(tot / (double)NVOX);
            g_sem = 0;   // reset for next graph replay
        }
    }
}

extern "C" void kernel_launch(void* const* d_in, const int* in_sizes, int n_in,
                              void* d_out, int out_size) {
    const float* I = (const float*)d_in[0];  // predicted
    const float* J = (const float*)d_in[1];  // target

    stats_h_kernel<<<(K1_THREADS + K1_BLK - 1) / K1_BLK, K1_BLK>>>(I, J);
    dwc_kernel<<<K2_BLOCKS, K2_THREADS>>>((float*)d_out);
}

// round 7
// speedup vs baseline: 3.4525x; 1.1127x over previous
#include <cuda_runtime.h>
#include <cuda_fp16.h>
#include <cstdint>

#define BB 2
#define DD 160
#define HH 192
#define WW 160
#define HW (HH*WW)               // 30720
#define DHW (DD*HH*WW)           // 4,915,200
#define NVOX (BB*DD*HH*WW)       // 9,830,400
#define NV4 (NVOX/4)             // 2,457,600
#define INV_WIN3 (1.0f/729.0f)

// ---------------- K1: stats + H box-sum (register ring, streaming) ----------
#define SEG_H1 12
#define SEGLEN_H1 (HH/SEG_H1)    // 16 (multiple of 8 -> compile-time ring slots)
#define COLS4 (BB*DD*WW/4)       // 12800 float4 columns
#define K1_THREADS (COLS4*SEG_H1)  // 153600
#define K1_BLK 256

// ---------------- K2: D-roll + W-roll + cc + reduce ----------------
#define ROWS2 4
#define SEG_D2 10
#define SEGLEN_D2 (DD/SEG_D2)    // 16
#define HTILES (HH/ROWS2)        // 48
#define K2_BLOCKS (BB*HTILES*SEG_D2)   // 960
#define K2_THREADS 160           // 4 rows x 40 float4-lanes
#define SMROW 42                 // float4s per padded row (1 pad + 40 + 1 pad)
#define SMBUF (5*ROWS2*SMROW)    // 840 float4 per buffer

// Packed fp16 H-summed stats (written once by K1, read by K2). ~98 MB total.
__device__ uint4 g_ab[NV4];      // ch0(I),  ch1(J)   : 8 halves
__device__ uint4 g_cd[NV4];      // ch2(I2), ch3(J2)  : 8 halves
__device__ uint2 g_e [NV4];      // ch4(IJ)           : 4 halves
__device__ double g_part[K2_BLOCKS];
__device__ int g_sem;            // self-resetting (0 at start of every replay)

__device__ __forceinline__ unsigned int pack2(float a, float b) {
    __half2 h = __floats2half2_rn(a, b);
    return *(unsigned int*)&h;
}
__device__ __forceinline__ float2 unpack2(unsigned int u) {
    __half2 h = *(__half2*)&u;
    return __half22float2(h);
}

__device__ __forceinline__ void acc_add(float4 s[5], float4 i, float4 j) {
    s[0].x+=i.x; s[0].y+=i.y; s[0].z+=i.z; s[0].w+=i.w;
    s[1].x+=j.x; s[1].y+=j.y; s[1].z+=j.z; s[1].w+=j.w;
    s[2].x+=i.x*i.x; s[2].y+=i.y*i.y; s[2].z+=i.z*i.z; s[2].w+=i.w*i.w;
    s[3].x+=j.x*j.x; s[3].y+=j.y*j.y; s[3].z+=j.z*j.z; s[3].w+=j.w*j.w;
    s[4].x+=i.x*j.x; s[4].y+=i.y*j.y; s[4].z+=i.z*j.z; s[4].w+=i.w*j.w;
}
__device__ __forceinline__ void acc_sub(float4 s[5], float4 i, float4 j) {
    s[0].x-=i.x; s[0].y-=i.y; s[0].z-=i.z; s[0].w-=i.w;
    s[1].x-=j.x; s[1].y-=j.y; s[1].z-=j.z; s[1].w-=j.w;
    s[2].x-=i.x*i.x; s[2].y-=i.y*i.y; s[2].z-=i.z*i.z; s[2].w-=i.w*i.w;
    s[3].x-=j.x*j.x; s[3].y-=j.y*j.y; s[3].z-=j.z*j.z; s[3].w-=j.w*j.w;
    s[4].x-=i.x*j.x; s[4].y-=i.y*j.y; s[4].z-=i.z*j.z; s[4].w-=i.w*j.w;
}

// ===========================================================================
// K1: thread = float4 column; 8-deep register ring of raw I,J rows; roll H.
// Outputs packed fp16 channel pairs.
// ===========================================================================
__global__ __launch_bounds__(K1_BLK) void stats_h_kernel(
    const float* __restrict__ I, const float* __restrict__ J) {
    int tid = blockIdx.x * K1_BLK + threadIdx.x;
    if (tid >= K1_THREADS) return;
    int col4 = tid % COLS4;
    int seg  = tid / COLS4;
    int b    = col4 / (DD * WW / 4);
    int rest = col4 % (DD * WW / 4);
    int d    = rest / (WW / 4);
    int w4   = rest % (WW / 4);
    const size_t base = (size_t)b * DHW + (size_t)d * HW + (size_t)w4 * 4;
    const int h0 = seg * SEGLEN_H1;   // multiple of 16

    float4 ringI[8], ringJ[8];
    float4 s[5];
    #pragma unroll
    for (int c = 0; c < 5; ++c) s[c] = make_float4(0.f,0.f,0.f,0.f);

    #pragma unroll
    for (int k = 0; k < 8; ++k) {
        int h = h0 - 4 + k;
        float4 i = make_float4(0.f,0.f,0.f,0.f), j = i;
        if (h >= 0 && h < HH) {
            i = __ldcs((const float4*)&I[base + (size_t)h * WW]);
            j = __ldcs((const float4*)&J[base + (size_t)h * WW]);
        }
        ringI[(k + 4) & 7] = i;
        ringJ[(k + 4) & 7] = j;
        acc_add(s, i, j);
    }

    for (int hb = h0; hb < h0 + SEGLEN_H1; hb += 8) {
        #pragma unroll
        for (int u = 0; u < 8; ++u) {
            const int slot = (u + 4) & 7;     // == (hb+u+4)&7 since hb%8==0
            int h  = hb + u;
            int ha = h + 4;
            float4 oi = ringI[slot], oj = ringJ[slot];
            float4 ni = make_float4(0.f,0.f,0.f,0.f), nj = ni;
            if (ha < HH) {
                ni = __ldcs((const float4*)&I[base + (size_t)ha * WW]);
                nj = __ldcs((const float4*)&J[base + (size_t)ha * WW]);
            }
            ringI[slot] = ni; ringJ[slot] = nj;
            acc_add(s, ni, nj);               // window now [h-4, h+4]
            size_t o4 = (base + (size_t)h * WW) >> 2;
            uint4 pab = make_uint4(pack2(s[0].x, s[0].y), pack2(s[0].z, s[0].w),
                                   pack2(s[1].x, s[1].y), pack2(s[1].z, s[1].w));
            uint4 pcd = make_uint4(pack2(s[2].x, s[2].y), pack2(s[2].z, s[2].w),
                                   pack2(s[3].x, s[3].y), pack2(s[3].z, s[3].w));
            uint2 pe  = make_uint2(pack2(s[4].x, s[4].y), pack2(s[4].z, s[4].w));
            __stcs(&g_ab[o4], pab);
            __stcs(&g_cd[o4], pcd);
            __stcs(&g_e [o4], pe);
            acc_sub(s, oi, oj);               // drop row h-4
        }
    }
}

// ===========================================================================
// K2: rolling D box-sum per float4 column (fp16-packed input, fp32 accum);
// per d-step stage into double-buffered smem (ONE barrier per step),
// 9-wide W windows + cc; global reduction with fused finalize.
// ===========================================================================
__device__ __forceinline__ float cc1(float s0, float s1, float s2, float s3,
                                     float s4) {
    float cross = fmaf(-s0 * INV_WIN3, s1, s4);
    float Ivar  = fmaf(-s0 * INV_WIN3, s0, s2);
    float Jvar  = fmaf(-s1 * INV_WIN3, s1, s3);
    return __fdividef(cross * cross, fmaf(Ivar, Jvar, 1e-5f));
}

__device__ __forceinline__ void load_add(float4 s[5], size_t o4, float sgn,
                                         bool evict) {
    uint4 vab = evict ? __ldcs(&g_ab[o4]) : __ldcg(&g_ab[o4]);
    uint4 vcd = evict ? __ldcs(&g_cd[o4]) : __ldcg(&g_cd[o4]);
    uint2 ve  = evict ? __ldcs(&g_e [o4]) : __ldcg(&g_e [o4]);
    float2 p;
    p = unpack2(vab.x); s[0].x += sgn*p.x; s[0].y += sgn*p.y;
    p = unpack2(vab.y); s[0].z += sgn*p.x; s[0].w += sgn*p.y;
    p = unpack2(vab.z); s[1].x += sgn*p.x; s[1].y += sgn*p.y;
    p = unpack2(vab.w); s[1].z += sgn*p.x; s[1].w += sgn*p.y;
    p = unpack2(vcd.x); s[2].x += sgn*p.x; s[2].y += sgn*p.y;
    p = unpack2(vcd.y); s[2].z += sgn*p.x; s[2].w += sgn*p.y;
    p = unpack2(vcd.z); s[3].x += sgn*p.x; s[3].y += sgn*p.y;
    p = unpack2(vcd.w); s[3].z += sgn*p.x; s[3].w += sgn*p.y;
    p = unpack2(ve.x);  s[4].x += sgn*p.x; s[4].y += sgn*p.y;
    p = unpack2(ve.y);  s[4].z += sgn*p.x; s[4].w += sgn*p.y;
}

__global__ __launch_bounds__(K2_THREADS) void dwc_kernel(float* __restrict__ out) {
    __shared__ float4 sm[2][SMBUF];            // double-buffered, 26,880 B
    __shared__ double wsum[K2_THREADS / 32];
    __shared__ bool is_last;

    int bx   = blockIdx.x;
    int dseg = bx % SEG_D2;
    int rest = bx / SEG_D2;
    int htile = rest % HTILES;
    int b     = rest / HTILES;
    int h0 = htile * ROWS2;
    int tid = threadIdx.x;
    int r  = tid / 40;
    int wi = tid % 40;

    for (int i = tid; i < 2 * SMBUF; i += K2_THREADS)
        sm[0][i] = make_float4(0.f, 0.f, 0.f, 0.f);   // zero both (pads!)

    const size_t colbase = (size_t)b * DHW + (size_t)(h0 + r) * WW + wi * 4;
    int d0 = dseg * SEGLEN_D2;

    float4 s[5];
    #pragma unroll
    for (int c = 0; c < 5; ++c) s[c] = make_float4(0.f, 0.f, 0.f, 0.f);

    int dp = d0 - 4 > 0 ? d0 - 4 : 0;
    for (int d = dp; d < d0 + 4; ++d)
        load_add(s, (colbase + (size_t)d * HW) >> 2, 1.f, false);
    __syncthreads();   // pads zeroed before first stage

    float acc = 0.f;
    int pb = 0;
    for (int dd = d0; dd < d0 + SEGLEN_D2; ++dd) {
        int da = dd + 4;
        if (da < DD)
            load_add(s, (colbase + (size_t)da * HW) >> 2, 1.f, false);

        float4* buf = sm[pb];
        #pragma unroll
        for (int c = 0; c < 5; ++c)
            buf[(c * ROWS2 + r) * SMROW + 1 + wi] = s[c];
        __syncthreads();   // the ONLY barrier per step (double-buffered)

        float win[5][4];
        #pragma unroll
        for (int c = 0; c < 5; ++c) {
            int rb = (c * ROWS2 + r) * SMROW + wi;
            float4 a0 = buf[rb], a1 = s[c], a2 = buf[rb + 2];
            float f0=a0.x,f1=a0.y,f2=a0.z,f3=a0.w;
            float f4_=a1.x,f5=a1.y,f6=a1.z,f7=a1.w;
            float f8=a2.x,f9=a2.y,f10=a2.z,f11=a2.w;
            float t = f0+f1+f2+f3+f4_+f5+f6+f7+f8;
            win[c][0] = t;
            t += f9  - f0; win[c][1] = t;
            t += f10 - f1; win[c][2] = t;
            t += f11 - f2; win[c][3] = t;
        }
        #pragma unroll
        for (int k = 0; k < 4; ++k)
            acc += cc1(win[0][k], win[1][k], win[2][k], win[3][k], win[4][k]);

        int ds = dd - 4;
        if (ds >= 0)   // L2 hit (8 steps of lag); dead after this read
            load_add(s, (colbase + (size_t)ds * HW) >> 2, -1.f, true);
        pb ^= 1;
    }

    #pragma unroll
    for (int off = 16; off; off >>= 1)
        acc += __shfl_down_sync(0xffffffffu, acc, off);
    int lane = tid & 31, wid = tid >> 5;
    if (lane == 0) wsum[wid] = (double)acc;
    __syncthreads();

    if (tid == 0) {
        double t = 0.0;
        #pragma unroll
        for (int i = 0; i < K2_THREADS / 32; ++i) t += wsum[i];
        g_part[bx] = t;
        __threadfence();
        int v = atomicAdd(&g_sem, 1);
        is_last = (v == gridDim.x - 1);
    }
    __syncthreads();

    if (is_last) {
        __threadfence();
        double t = 0.0;
        for (int i = tid; i < K2_BLOCKS; i += K2_THREADS) t += g_part[i];
        #pragma unroll
        for (int off = 16; off; off >>= 1)
            t += __shfl_down_sync(0xffffffffu, t, off);
        if (lane == 0) wsum[wid] = t;
        __syncthreads();
        if (tid == 0) {
            double tot = 0.0;
            #pragma unroll
            for (int i = 0; i < K2_THREADS / 32; ++i) tot += wsum[i];
            out[0] = (float)(tot / (double)NVOX);
            g_sem = 0;   // reset for next graph replay
        }
    }
}

extern "C" void kernel_launch(void* const* d_in, const int* in_sizes, int n_in,
                              void* d_out, int out_size) {
    const float* I = (const float*)d_in[0];  // predicted
    const float* J = (const float*)d_in[1];  // target

    stats_h_kernel<<<(K1_THREADS + K1_BLK - 1) / K1_BLK, K1_BLK>>>(I, J);
    dwc_kernel<<<K2_BLOCKS, K2_THREADS>>>((float*)d_out);
}

// round 9
// speedup vs baseline: 4.9485x; 1.4333x over previous
#include <cuda_runtime.h>
#include <cuda_fp16.h>
#include <cstdint>

#define BB 2
#define DD 160
#define HH 192
#define WW 160
#define HW (HH*WW)               // 30720
#define DHW (DD*HH*WW)           // 4,915,200
#define NVOX (BB*DD*HH*WW)       // 9,830,400
#define NV4 (NVOX/4)             // 2,457,600
#define INV_WIN3 (1.0f/729.0f)

// ---------------- K1: stats + H box-sum (fp16 ring + prefetch) ----------
#define SEG_H1 12
#define SEGLEN_H1 (HH/SEG_H1)    // 16 (multiple of 8 -> compile-time ring slots)
#define COLS4 (BB*DD*WW/4)       // 12800 float4 columns
#define K1_THREADS (COLS4*SEG_H1)  // 153600
#define K1_BLK 256

// ---------------- K2: D-roll + W-roll + cc + reduce ----------------
#define ROWS2 4
#define SEG_D2 10
#define SEGLEN_D2 (DD/SEG_D2)    // 16
#define HTILES (HH/ROWS2)        // 48
#define K2_BLOCKS (BB*HTILES*SEG_D2)   // 960
#define K2_THREADS 160           // 4 rows x 40 float4-lanes
#define SMROW 42                 // float4s per padded row (1 pad + 40 + 1 pad)
#define SMBUF (5*ROWS2*SMROW)    // 840 float4 per buffer

// Packed fp16 H-summed stats (written once by K1, read by K2). ~98 MB total.
__device__ uint4 g_ab[NV4];      // ch0(I),  ch1(J)   : 8 halves
__device__ uint4 g_cd[NV4];      // ch2(I2), ch3(J2)  : 8 halves
__device__ uint2 g_e [NV4];      // ch4(IJ)           : 4 halves
__device__ double g_part[K2_BLOCKS];
__device__ int g_sem;            // self-resetting (0 at start of every replay)

__device__ __forceinline__ unsigned int pack2(float a, float b) {
    __half2 h = __floats2half2_rn(a, b);
    return *(unsigned int*)&h;
}
__device__ __forceinline__ float2 unpack2(unsigned int u) {
    __half2 h = *(__half2*)&u;
    return __half22float2(h);
}
__device__ __forceinline__ uint2 packf4(float4 v) {
    uint2 r; r.x = pack2(v.x, v.y); r.y = pack2(v.z, v.w); return r;
}
__device__ __forceinline__ float4 unpackf4(uint2 u) {
    float2 a = unpack2(u.x), b = unpack2(u.y);
    return make_float4(a.x, a.y, b.x, b.y);
}

__device__ __forceinline__ void acc_add(float4 s[5], float4 i, float4 j) {
    s[0].x+=i.x; s[0].y+=i.y; s[0].z+=i.z; s[0].w+=i.w;
    s[1].x+=j.x; s[1].y+=j.y; s[1].z+=j.z; s[1].w+=j.w;
    s[2].x+=i.x*i.x; s[2].y+=i.y*i.y; s[2].z+=i.z*i.z; s[2].w+=i.w*i.w;
    s[3].x+=j.x*j.x; s[3].y+=j.y*j.y; s[3].z+=j.z*j.z; s[3].w+=j.w*j.w;
    s[4].x+=i.x*j.x; s[4].y+=i.y*j.y; s[4].z+=i.z*j.z; s[4].w+=i.w*j.w;
}
__device__ __forceinline__ void acc_sub(float4 s[5], float4 i, float4 j) {
    s[0].x-=i.x; s[0].y-=i.y; s[0].z-=i.z; s[0].w-=i.w;
    s[1].x-=j.x; s[1].y-=j.y; s[1].z-=j.z; s[1].w-=j.w;
    s[2].x-=i.x*i.x; s[2].y-=i.y*i.y; s[2].z-=i.z*i.z; s[2].w-=i.w*i.w;
    s[3].x-=j.x*j.x; s[3].y-=j.y*j.y; s[3].z-=j.z*j.z; s[3].w-=j.w*j.w;
    s[4].x-=i.x*j.x; s[4].y-=i.y*j.y; s[4].z-=i.z*j.z; s[4].w-=i.w*j.w;
}

// ===========================================================================
// K1: thread = float4 column. Inputs rounded to fp16 at load; ring stores the
// PACKED rounded rows (32 regs), so rolling add/sub cancels exactly. Next
// step's loads prefetched before current accumulation chain (MLP 4).
// ===========================================================================
__global__ __launch_bounds__(K1_BLK) void stats_h_kernel(
    const float* __restrict__ I, const float* __restrict__ J) {
    int tid = blockIdx.x * K1_BLK + threadIdx.x;
    if (tid >= K1_THREADS) return;
    int col4 = tid % COLS4;
    int seg  = tid / COLS4;
    int b    = col4 / (DD * WW / 4);
    int rest = col4 % (DD * WW / 4);
    int d    = rest / (WW / 4);
    int w4   = rest % (WW / 4);
    const size_t base = (size_t)b * DHW + (size_t)d * HW + (size_t)w4 * 4;
    const int h0 = seg * SEGLEN_H1;   // multiple of 16

    uint2 ringI[8], ringJ[8];
    float4 s[5];
    #pragma unroll
    for (int c = 0; c < 5; ++c) s[c] = make_float4(0.f,0.f,0.f,0.f);

    #pragma unroll
    for (int k = 0; k < 8; ++k) {
        int h = h0 - 4 + k;
        float4 i = make_float4(0.f,0.f,0.f,0.f), j = i;
        if (h >= 0 && h < HH) {
            i = __ldcs((const float4*)&I[base + (size_t)h * WW]);
            j = __ldcs((const float4*)&J[base + (size_t)h * WW]);
        }
        uint2 ip = packf4(i), jp = packf4(j);
        ringI[(k + 4) & 7] = ip;
        ringJ[(k + 4) & 7] = jp;
        acc_add(s, unpackf4(ip), unpackf4(jp));
    }

    // Prefetch the row for the first main step (h0+4).
    float4 pi = make_float4(0.f,0.f,0.f,0.f), pj = pi;
    if (h0 + 4 < HH) {
        pi = __ldcs((const float4*)&I[base + (size_t)(h0 + 4) * WW]);
        pj = __ldcs((const float4*)&J[base + (size_t)(h0 + 4) * WW]);
    }

    for (int hb = h0; hb < h0 + SEGLEN_H1; hb += 8) {
        #pragma unroll
        for (int u = 0; u < 8; ++u) {
            const int slot = (u + 4) & 7;     // == (hb+u+4)&7 since hb%8==0
            int h  = hb + u;
            uint2 nip = packf4(pi), njp = packf4(pj);
            // prefetch next step's row (h+5) — independent, issues early
            int hn = h + 5;
            float4 npi = make_float4(0.f,0.f,0.f,0.f), npj = npi;
            if (hn < HH) {
                npi = __ldcs((const float4*)&I[base + (size_t)hn * WW]);
                npj = __ldcs((const float4*)&J[base + (size_t)hn * WW]);
            }
            acc_add(s, unpackf4(nip), unpackf4(njp));  // window now [h-4,h+4]
            size_t o4 = (base + (size_t)h * WW) >> 2;
            uint4 pab = make_uint4(pack2(s[0].x, s[0].y), pack2(s[0].z, s[0].w),
                                   pack2(s[1].x, s[1].y), pack2(s[1].z, s[1].w));
            uint4 pcd = make_uint4(pack2(s[2].x, s[2].y), pack2(s[2].z, s[2].w),
                                   pack2(s[3].x, s[3].y), pack2(s[3].z, s[3].w));
            uint2 pe  = make_uint2(pack2(s[4].x, s[4].y), pack2(s[4].z, s[4].w));
            __stcs(&g_ab[o4], pab);
            __stcs(&g_cd[o4], pcd);
            __stcs(&g_e [o4], pe);
            acc_sub(s, unpackf4(ringI[slot]), unpackf4(ringJ[slot]));  // exact
            ringI[slot] = nip; ringJ[slot] = njp;
            pi = npi; pj = npj;
        }
    }
}

// ===========================================================================
// K2: rolling D box-sum per float4 column; fused diff update (HSUB2 on packed
// fp16), double-buffered smem stage (one barrier/step), 9-wide W windows + cc,
// global reduction with fused finalize.
// Recurrence: window(dd) = window(dd-1) + row(dd+4) - row(dd-5), so the
// prime sum must cover [max(0, d0-5), d0+3].
// ===========================================================================
__device__ __forceinline__ float cc1(float s0, float s1, float s2, float s3,
                                     float s4) {
    float cross = fmaf(-s0 * INV_WIN3, s1, s4);
    float Ivar  = fmaf(-s0 * INV_WIN3, s0, s2);
    float Jvar  = fmaf(-s1 * INV_WIN3, s1, s3);
    return __fdividef(cross * cross, fmaf(Ivar, Jvar, 1e-5f));
}

__device__ __forceinline__ void load_add(float4 s[5], size_t o4, float sgn) {
    uint4 vab = __ldcg(&g_ab[o4]);
    uint4 vcd = __ldcg(&g_cd[o4]);
    uint2 ve  = __ldcg(&g_e [o4]);
    float2 p;
    p = unpack2(vab.x); s[0].x += sgn*p.x; s[0].y += sgn*p.y;
    p = unpack2(vab.y); s[0].z += sgn*p.x; s[0].w += sgn*p.y;
    p = unpack2(vab.z); s[1].x += sgn*p.x; s[1].y += sgn*p.y;
    p = unpack2(vab.w); s[1].z += sgn*p.x; s[1].w += sgn*p.y;
    p = unpack2(vcd.x); s[2].x += sgn*p.x; s[2].y += sgn*p.y;
    p = unpack2(vcd.y); s[2].z += sgn*p.x; s[2].w += sgn*p.y;
    p = unpack2(vcd.z); s[3].x += sgn*p.x; s[3].y += sgn*p.y;
    p = unpack2(vcd.w); s[3].z += sgn*p.x; s[3].w += sgn*p.y;
    p = unpack2(ve.x);  s[4].x += sgn*p.x; s[4].y += sgn*p.y;
    p = unpack2(ve.y);  s[4].z += sgn*p.x; s[4].w += sgn*p.y;
}

__device__ __forceinline__ void hdiff_add(float& x, float& y,
                                          unsigned int a, unsigned int b) {
    __half2 ha = *(__half2*)&a, hb = *(__half2*)&b;
    __half2 d = __hsub2(ha, hb);
    float2 p = __half22float2(d);
    x += p.x; y += p.y;
}

// s += row(oa) - row(os), diff computed in packed fp16 (HSUB2): ~30 fewer
// instructions than separate add+sub streams.
__device__ __forceinline__ void load_diff_add(float4 s[5], size_t oa, size_t os) {
    uint4 Aab = __ldcg(&g_ab[oa]); uint4 Bab = __ldcs(&g_ab[os]);
    uint4 Acd = __ldcg(&g_cd[oa]); uint4 Bcd = __ldcs(&g_cd[os]);
    uint2 Ae  = __ldcg(&g_e [oa]); uint2 Be  = __ldcs(&g_e [os]);
    hdiff_add(s[0].x, s[0].y, Aab.x, Bab.x);
    hdiff_add(s[0].z, s[0].w, Aab.y, Bab.y);
    hdiff_add(s[1].x, s[1].y, Aab.z, Bab.z);
    hdiff_add(s[1].z, s[1].w, Aab.w, Bab.w);
    hdiff_add(s[2].x, s[2].y, Acd.x, Bcd.x);
    hdiff_add(s[2].z, s[2].w, Acd.y, Bcd.y);
    hdiff_add(s[3].x, s[3].y, Acd.z, Bcd.z);
    hdiff_add(s[3].z, s[3].w, Acd.w, Bcd.w);
    hdiff_add(s[4].x, s[4].y, Ae.x,  Be.x);
    hdiff_add(s[4].z, s[4].w, Ae.y,  Be.y);
}

__global__ __launch_bounds__(K2_THREADS) void dwc_kernel(float* __restrict__ out) {
    __shared__ float4 sm[2][SMBUF];            // double-buffered, 26,880 B
    __shared__ double wsum[K2_THREADS / 32];
    __shared__ bool is_last;

    int bx   = blockIdx.x;
    int dseg = bx % SEG_D2;
    int rest = bx / SEG_D2;
    int htile = rest % HTILES;
    int b     = rest / HTILES;
    int h0 = htile * ROWS2;
    int tid = threadIdx.x;
    int r  = tid / 40;
    int wi = tid % 40;

    for (int i = tid; i < 2 * SMBUF; i += K2_THREADS)
        sm[0][i] = make_float4(0.f, 0.f, 0.f, 0.f);   // zero both (pads!)

    const size_t colbase = (size_t)b * DHW + (size_t)(h0 + r) * WW + wi * 4;
    int d0 = dseg * SEGLEN_D2;

    float4 s[5];
    #pragma unroll
    for (int c = 0; c < 5; ++c) s[c] = make_float4(0.f, 0.f, 0.f, 0.f);

    // Prime: s = sum rows [max(0, d0-5), d0+3]  (pre-window for the
    // start-of-step recurrence: first step adds d0+4 and removes d0-5).
    int dp = d0 - 5 > 0 ? d0 - 5 : 0;
    for (int d = dp; d < d0 + 4; ++d)
        load_add(s, (colbase + (size_t)d * HW) >> 2, 1.f);
    __syncthreads();   // pads zeroed before first stage

    float acc = 0.f;
    int pb = 0;
    for (int dd = d0; dd < d0 + SEGLEN_D2; ++dd) {
        // Update at START of step: add row dd+4, remove row dd-5.
        int da = dd + 4, ds = dd - 5;
        if (da < DD && ds >= 0) {
            load_diff_add(s, (colbase + (size_t)da * HW) >> 2,
                             (colbase + (size_t)ds * HW) >> 2);
        } else {
            if (da < DD) load_add(s, (colbase + (size_t)da * HW) >> 2,  1.f);
            if (ds >= 0) load_add(s, (colbase + (size_t)ds * HW) >> 2, -1.f);
        }

        float4* buf = sm[pb];
        #pragma unroll
        for (int c = 0; c < 5; ++c)
            buf[(c * ROWS2 + r) * SMROW + 1 + wi] = s[c];
        __syncthreads();   // the ONLY barrier per step (double-buffered)

        float win[5][4];
        #pragma unroll
        for (int c = 0; c < 5; ++c) {
            int rb = (c * ROWS2 + r) * SMROW + wi;
            float4 a0 = buf[rb], a1 = s[c], a2 = buf[rb + 2];
            float f0=a0.x,f1=a0.y,f2=a0.z,f3=a0.w;
            float f4_=a1.x,f5=a1.y,f6=a1.z,f7=a1.w;
            float f8=a2.x,f9=a2.y,f10=a2.z,f11=a2.w;
            float t = f0+f1+f2+f3+f4_+f5+f6+f7+f8;
            win[c][0] = t;
            t += f9  - f0; win[c][1] = t;
            t += f10 - f1; win[c][2] = t;
            t += f11 - f2; win[c][3] = t;
        }
        #pragma unroll
        for (int k = 0; k < 4; ++k)
            acc += cc1(win[0][k], win[1][k], win[2][k], win[3][k], win[4][k]);
        pb ^= 1;
    }

    #pragma unroll
    for (int off = 16; off; off >>= 1)
        acc += __shfl_down_sync(0xffffffffu, acc, off);
    int lane = tid & 31, wid = tid >> 5;
    if (lane == 0) wsum[wid] = (double)acc;
    __syncthreads();

    if (tid == 0) {
        double t = 0.0;
        #pragma unroll
        for (int i = 0; i < K2_THREADS / 32; ++i) t += wsum[i];
        g_part[bx] = t;
        __threadfence();
        int v = atomicAdd(&g_sem, 1);
        is_last = (v == gridDim.x - 1);
    }
    __syncthreads();

    if (is_last) {
        __threadfence();
        double t = 0.0;
        for (int i = tid; i < K2_BLOCKS; i += K2_THREADS) t += g_part[i];
        #pragma unroll
        for (int off = 16; off; off >>= 1)
            t += __shfl_down_sync(0xffffffffu, t, off);
        if (lane == 0) wsum[wid] = t;
        __syncthreads();
        if (tid == 0) {
            double tot = 0.0;
            #pragma unroll
            for (int i = 0; i < K2_THREADS / 32; ++i) tot += wsum[i];
            out[0] = (float)(tot / (double)NVOX);
            g_sem = 0;   // reset for next graph replay
        }
    }
}

extern "C" void kernel_launch(void* const* d_in, const int* in_sizes, int n_in,
                              void* d_out, int out_size) {
    const float* I = (const float*)d_in[0];  // predicted
    const float* J = (const float*)d_in[1];  // target

    stats_h_kernel<<<(K1_THREADS + K1_BLK - 1) / K1_BLK, K1_BLK>>>(I, J);
    dwc_kernel<<<K2_BLOCKS, K2_THREADS>>>((float*)d_out);
}